// round 10
// baseline (speedup 1.0000x reference)
#include <cuda_runtime.h>
#include <cuda_bf16.h>
#include <math.h>
#include <stdint.h>

// ---------------- problem constants ----------------
#define BB 8
#define TT 2048
#define DD 128
#define HH 4
#define HD 32
#define DH 64
#define NTOK (BB*TT)
#define SCALE 0.17677669529663687f
#define LOG2E 1.4426950408889634f
#define LAMBDA_INIT 0.8f
#define LN_EPS 1e-5f
#define BAND 64

// ---------------- scratch ----------------
__device__ float g_xnorm[NTOK * DD];
__device__ float g_Q[BB*HH*TT*DH];
__device__ float g_K[BB*HH*TT*DH];
__device__ float g_V[BB*HH*TT*DH];
__device__ float g_O[NTOK * 256];

// ---------------- helpers ----------------
__device__ __forceinline__ uint32_t f2tf(float x){
    uint32_t r; asm("cvt.rna.tf32.f32 %0, %1;" : "=r"(r) : "f"(x)); return r;
}
__device__ __forceinline__ float tfr(float x){ return __uint_as_float(f2tf(x)); }

__device__ __forceinline__ void mma8(float4& d, const uint32_t* a, const uint32_t* b, const float4& c){
    asm volatile("mma.sync.aligned.m16n8k8.row.col.f32.tf32.tf32.f32 "
        "{%0,%1,%2,%3}, {%4,%5,%6,%7}, {%8,%9}, {%10,%11,%12,%13};"
        : "=f"(d.x),"=f"(d.y),"=f"(d.z),"=f"(d.w)
        : "r"(a[0]),"r"(a[1]),"r"(a[2]),"r"(a[3]),
          "r"(b[0]),"r"(b[1]),
          "f"(c.x),"f"(c.y),"f"(c.z),"f"(c.w));
}
__device__ __forceinline__ void cp16(float* smem, const float* gmem){
    uint32_t s = (uint32_t)__cvta_generic_to_shared(smem);
    asm volatile("cp.async.cg.shared.global [%0], [%1], 16;" :: "r"(s), "l"(gmem));
}
#define CP_COMMIT asm volatile("cp.async.commit_group;")
#define CP_WAIT0 asm volatile("cp.async.wait_group 0;")
#define CP_WAIT1 asm volatile("cp.async.wait_group 1;")

// ================= K0: layernorm (tf32-rounded output) =================
__global__ __launch_bounds__(256) void ln_kernel(const float* __restrict__ x,
                                                 const float* __restrict__ w,
                                                 const float* __restrict__ b){
    int token = blockIdx.x * 8 + threadIdx.y;
    int lane  = threadIdx.x;
    const float4* xr = (const float4*)(x + (size_t)token * DD);
    float4 v = xr[lane];
    float s = v.x + v.y + v.z + v.w;
    #pragma unroll
    for (int o = 16; o; o >>= 1) s += __shfl_xor_sync(0xffffffffu, s, o);
    float mu = s * (1.0f / DD);
    float dx0 = v.x - mu, dx1 = v.y - mu, dx2 = v.z - mu, dx3 = v.w - mu;
    float sq = dx0*dx0 + dx1*dx1 + dx2*dx2 + dx3*dx3;
    #pragma unroll
    for (int o = 16; o; o >>= 1) sq += __shfl_xor_sync(0xffffffffu, sq, o);
    float rstd = rsqrtf(sq * (1.0f / DD) + LN_EPS);
    float4 wv = ((const float4*)w)[lane];
    float4 bv = ((const float4*)b)[lane];
    float4 out;
    out.x = tfr(dx0 * rstd * wv.x + bv.x);
    out.y = tfr(dx1 * rstd * wv.y + bv.y);
    out.z = tfr(dx2 * rstd * wv.z + bv.z);
    out.w = tfr(dx3 * rstd * wv.w + bv.w);
    ((float4*)(g_xnorm + (size_t)token * DD))[lane] = out;
}

// ================= K1: QKV GEMM tf32 (16384 x 768 x 128), 2-stage cp.async =================
#define QKV_SAT (128*36)
#define QKV_SBT (32*136)
__global__ __launch_bounds__(256) void qkv_gemm(const float* __restrict__ wq,
                                                const float* __restrict__ wk,
                                                const float* __restrict__ wv){
    extern __shared__ float dynsm[];
    float* sA = dynsm;
    float* sB = dynsm + 2*QKV_SAT;

    int brow = blockIdx.x, bc = blockIdx.y;
    int tid = threadIdx.x;
    int w = tid >> 5, lane = tid & 31, g = lane >> 2, q = lane & 3;
    int wm = w >> 2, wn = w & 3;
    const float* W = (bc < 2) ? wq : (bc < 4 ? wk : wv);
    int colbase = (bc & 1) * 128;
    float4 acc[4][4];
    #pragma unroll
    for (int i = 0; i < 4; i++)
        #pragma unroll
        for (int j = 0; j < 4; j++) acc[i][j] = make_float4(0.f,0.f,0.f,0.f);

    #pragma unroll
    for (int f = tid; f < 1024; f += 256){
        int r = f >> 3, c4 = f & 7;
        cp16(sA + r*36 + c4*4, g_xnorm + (size_t)(brow*128 + r)*DD + c4*4);
    }
    #pragma unroll
    for (int f = tid; f < 1024; f += 256){
        int kr = f >> 5, c4 = f & 31;
        cp16(sB + kr*136 + c4*4, W + (size_t)kr*256 + colbase + c4*4);
    }
    CP_COMMIT;

    for (int kc = 0; kc < 4; kc++){
        if (kc + 1 < 4){
            float* dA = sA + ((kc+1)&1)*QKV_SAT;
            float* dB = sB + ((kc+1)&1)*QKV_SBT;
            #pragma unroll
            for (int f = tid; f < 1024; f += 256){
                int r = f >> 3, c4 = f & 7;
                cp16(dA + r*36 + c4*4, g_xnorm + (size_t)(brow*128 + r)*DD + (kc+1)*32 + c4*4);
            }
            #pragma unroll
            for (int f = tid; f < 1024; f += 256){
                int kr = f >> 5, c4 = f & 31;
                cp16(dB + kr*136 + c4*4, W + (size_t)((kc+1)*32 + kr)*256 + colbase + c4*4);
            }
            CP_COMMIT;
            CP_WAIT1;
        } else {
            CP_WAIT0;
        }
        __syncthreads();
        const float* sAc = sA + (kc&1)*QKV_SAT;
        const float* sBc = sB + (kc&1)*QKV_SBT;
        #pragma unroll
        for (int ks = 0; ks < 4; ks++){
            uint32_t a[4][4];
            int kk = ks*8 + q;
            #pragma unroll
            for (int mt = 0; mt < 4; mt++){
                int r = wm*64 + mt*16 + g;
                a[mt][0] = __float_as_uint(sAc[r*36 + kk]);
                a[mt][1] = __float_as_uint(sAc[(r+8)*36 + kk]);
                a[mt][2] = __float_as_uint(sAc[r*36 + kk + 4]);
                a[mt][3] = __float_as_uint(sAc[(r+8)*36 + kk + 4]);
            }
            #pragma unroll
            for (int nt = 0; nt < 4; nt++){
                uint32_t b[2];
                int n = wn*32 + nt*8 + g;
                b[0] = __float_as_uint(sBc[kk*136 + n]);
                b[1] = __float_as_uint(sBc[(kk+4)*136 + n]);
                #pragma unroll
                for (int mt = 0; mt < 4; mt++)
                    mma8(acc[mt][nt], a[mt], b, acc[mt][nt]);
            }
        }
        __syncthreads();
    }

    int mat = bc >> 1;
    float* dst = (mat == 0) ? g_Q : (mat == 1 ? g_K : g_V);
    #pragma unroll
    for (int mt = 0; mt < 4; mt++){
        int r0 = brow*128 + wm*64 + mt*16 + g;
        int r1 = r0 + 8;
        int b0_ = r0 >> 11, t0 = r0 & (TT-1);
        int b1_ = r1 >> 11, t1 = r1 & (TT-1);
        #pragma unroll
        for (int nt = 0; nt < 4; nt++){
            int col = colbase + wn*32 + nt*8 + 2*q;
            int head = col >> 6, dim = col & 63;
            float* p0 = dst + ((size_t)((b0_*HH + head)*TT + t0))*DH + dim;
            float* p1 = dst + ((size_t)((b1_*HH + head)*TT + t1))*DH + dim;
            *(float2*)p0 = make_float2(tfr(acc[mt][nt].x), tfr(acc[mt][nt].y));
            *(float2*)p1 = make_float2(tfr(acc[mt][nt].z), tfr(acc[mt][nt].w));
        }
    }
}

// ================= K2: branch-parallel banded attention, KTILE=32, smem overlay, tile skip =================
// 256 threads, 8 warps: (branch bw) x (16-row strip wq). Overlay region (4608 floats):
//   phase A: sQ [64][68] (dead after Q-frag preload)
//   phase B: per-warp P tiles, 8 x [16][36]
//   phase C: combine buffer [64][72]
#define KT 32
#define SKT (KT*68)
#define SVT (KT*72)
#define SPW (16*36)
#define OVR 4608
__global__ __launch_bounds__(256, 3) void attn_kernel(
        const float* __restrict__ lq1, const float* __restrict__ lk1,
        const float* __restrict__ lq2, const float* __restrict__ lk2,
        const float* __restrict__ sig_s_p, const float* __restrict__ sig_n_p,
        const float* __restrict__ hnw, const float* __restrict__ hnb){
    extern __shared__ float dynsm[];
    float* sOv = dynsm;             // overlay region (OVR floats)
    float* sQ  = sOv;               // [64][68], phase A
    float* sK  = dynsm + OVR;       // 2 stages [32 keys][68]
    float* sV  = sK + 2*SKT;        // 2 stages [32 keys][72]

    int bh = blockIdx.y;
    int q0 = blockIdx.x * 64;
    int tid = threadIdx.x;
    int w = tid >> 5, lane = tid & 31, g = lane >> 2, q = lane & 3;
    int bw = w & 1, wq = w >> 1;
    float* sP = sOv + w*SPW;        // phase B

    const float* Qb = g_Q + (size_t)bh * TT * DH;
    const float* Kb = g_K + (size_t)bh * TT * DH;
    const float* Vb = g_V + (size_t)bh * TT * DH;

    int klo = q0 - BAND; if (klo < 0) klo = 0;
    int khi = q0 + 64 + BAND; if (khi > TT) khi = TT;
    int ntile = (khi - klo) >> 5;

    // strip band for tile skipping
    int rlo = q0 + wq*16, rhi = rlo + 15;

    #pragma unroll
    for (int f = tid; f < 1024; f += 256){
        int r = f >> 4, c4 = f & 15;
        cp16(sQ + r*68 + c4*4, Qb + (size_t)(q0 + r)*DH + c4*4);
    }
    CP_COMMIT;
    #pragma unroll
    for (int f = tid; f < 512; f += 256){
        int kk = f >> 4, c4 = f & 15;
        cp16(sK + kk*68 + c4*4, Kb + (size_t)(klo + kk)*DH + c4*4);
        cp16(sV + kk*72 + c4*4, Vb + (size_t)(klo + kk)*DH + c4*4);
    }
    CP_COMMIT;

    float e1 = 0.f, e2 = 0.f;
    #pragma unroll
    for (int i = 0; i < HD; i++){ e1 += lq1[i]*lk1[i]; e2 += lq2[i]*lk2[i]; }
    float lam = __expf(e1) - __expf(e2) + LAMBDA_INIT;
    float sig_s = fmaxf(sig_s_p[0], 1.0f), sig_n = fmaxf(sig_n_p[0], 1.0f);
    float sc2 = SCALE * LOG2E;
    float cb = bw ? (-0.5f * LOG2E / (sig_n * sig_n))
                  : (-0.5f * LOG2E / (sig_s * sig_s));

    CP_WAIT1;   // sQ ready
    __syncthreads();

    // phase A -> registers: preload Q a-frags for this warp's branch + strip
    uint32_t qa[4][4];
    {
        int rb = (wq*16 + g)*68 + bw*32;
        #pragma unroll
        for (int ks = 0; ks < 4; ks++){
            int d0 = ks*8 + q;
            qa[ks][0] = __float_as_uint(sQ[rb + d0]);
            qa[ks][1] = __float_as_uint(sQ[rb + 8*68 + d0]);
            qa[ks][2] = __float_as_uint(sQ[rb + d0 + 4]);
            qa[ks][3] = __float_as_uint(sQ[rb + 8*68 + d0 + 4]);
        }
    }

    float4 o[8];
    #pragma unroll
    for (int nt = 0; nt < 8; nt++) o[nt] = make_float4(0.f,0.f,0.f,0.f);
    float l_lo = 0.f, l_hi = 0.f;

    float row_lo = (float)(q0 + wq*16 + g);
    float row_hi = row_lo + 8.0f;

    for (int it = 0; it < ntile; it++){
        int ksb = klo + it*KT;
        if (it + 1 < ntile){
            float* dK = sK + ((it+1)&1)*SKT;
            float* dV = sV + ((it+1)&1)*SVT;
            int kn = klo + (it+1)*KT;
            #pragma unroll
            for (int f = tid; f < 512; f += 256){
                int kk = f >> 4, c4 = f & 15;
                cp16(dK + kk*68 + c4*4, Kb + (size_t)(kn + kk)*DH + c4*4);
                cp16(dV + kk*72 + c4*4, Vb + (size_t)(kn + kk)*DH + c4*4);
            }
            CP_COMMIT;
            CP_WAIT1;
        } else {
            CP_WAIT0;
        }
        __syncthreads();   // phase B active: sP valid, sQ dead

        // per-warp band overlap test (warp-uniform, no divergence)
        bool needed = (ksb <= rhi + BAND) && (ksb + KT - 1 >= rlo - BAND);
        if (needed){
            const float* sKc = sK + (it&1)*SKT;
            const float* sVc = sV + (it&1)*SVT;

            // ---- scores over 32 keys (this warp's branch) ----
            float4 s[4];
            #pragma unroll
            for (int nt = 0; nt < 4; nt++) s[nt] = make_float4(0.f,0.f,0.f,0.f);
            #pragma unroll
            for (int ks = 0; ks < 4; ks++){
                int d0 = ks*8 + q + bw*32;
                #pragma unroll
                for (int nt = 0; nt < 4; nt++){
                    uint32_t b[2];
                    int kb = (nt*8 + g)*68 + d0;
                    b[0] = __float_as_uint(sKc[kb]);
                    b[1] = __float_as_uint(sKc[kb + 4]);
                    mma8(s[nt], qa[ks], b, s[nt]);
                }
            }

            // ---- bias + exp (fixed reference) -> P smem ----
            #pragma unroll
            for (int nt = 0; nt < 4; nt++){
                float k0f = (float)(ksb + nt*8 + 2*q);
                float rx_lo = k0f - row_lo,  ry_lo = k0f + 1.0f - row_lo;
                float rx_hi = k0f - row_hi,  ry_hi = k0f + 1.0f - row_hi;
                float ax = exp2f(s[nt].x*sc2 + rx_lo*rx_lo*cb);
                float ay = exp2f(s[nt].y*sc2 + ry_lo*ry_lo*cb);
                float az = exp2f(s[nt].z*sc2 + rx_hi*rx_hi*cb);
                float aw = exp2f(s[nt].w*sc2 + ry_hi*ry_hi*cb);
                l_lo += ax + ay;  l_hi += az + aw;
                *(float2*)(sP + g*36 + nt*8 + 2*q)     = make_float2(ax, ay);
                *(float2*)(sP + (g+8)*36 + nt*8 + 2*q) = make_float2(az, aw);
            }
            __syncwarp();

            // ---- PV: O += P V ----
            #pragma unroll
            for (int ks = 0; ks < 4; ks++){
                uint32_t a[4];
                int pk = ks*8 + q;
                a[0] = __float_as_uint(sP[g*36 + pk]);
                a[1] = __float_as_uint(sP[(g+8)*36 + pk]);
                a[2] = __float_as_uint(sP[g*36 + pk + 4]);
                a[3] = __float_as_uint(sP[(g+8)*36 + pk + 4]);
                int kv = ks*8 + q;
                #pragma unroll
                for (int nt = 0; nt < 8; nt++){
                    uint32_t b[2];
                    b[0] = __float_as_uint(sVc[kv*72 + nt*8 + g]);
                    b[1] = __float_as_uint(sVc[(kv+4)*72 + nt*8 + g]);
                    mma8(o[nt], a, b, o[nt]);
                }
            }
            __syncwarp();
        }
        __syncthreads();   // K/V stage consumed before next prefetch overwrites
    }

    // ---- reduce l over quad ----
    #pragma unroll
    for (int os = 1; os <= 2; os <<= 1){
        l_lo += __shfl_xor_sync(0xffffffffu, l_lo, os);
        l_hi += __shfl_xor_sync(0xffffffffu, l_hi, os);
    }

    // ---- phase C: branch combine via overlay buffer [64][72] ----
    if (bw == 1){
        float s_lo = lam / l_lo, s_hi = lam / l_hi;
        int rb0 = (wq*16 + g)*72, rb1 = (wq*16 + g + 8)*72;
        #pragma unroll
        for (int nt = 0; nt < 8; nt++){
            *(float2*)(sOv + rb0 + nt*8 + 2*q) = make_float2(o[nt].x*s_lo, o[nt].y*s_lo);
            *(float2*)(sOv + rb1 + nt*8 + 2*q) = make_float2(o[nt].z*s_hi, o[nt].w*s_hi);
        }
    }
    __syncthreads();
    if (bw == 0){
        float i_lo = 1.0f / l_lo, i_hi = 1.0f / l_hi;
        int rb0 = (wq*16 + g)*72, rb1 = (wq*16 + g + 8)*72;
        float4 ov[8];
        float slo = 0.f, shi = 0.f;
        #pragma unroll
        for (int nt = 0; nt < 8; nt++){
            float2 c0 = *(const float2*)(sOv + rb0 + nt*8 + 2*q);
            float2 c1 = *(const float2*)(sOv + rb1 + nt*8 + 2*q);
            ov[nt].x = o[nt].x*i_lo - c0.x;
            ov[nt].y = o[nt].y*i_lo - c0.y;
            ov[nt].z = o[nt].z*i_hi - c1.x;
            ov[nt].w = o[nt].w*i_hi - c1.y;
            slo += ov[nt].x + ov[nt].y;
            shi += ov[nt].z + ov[nt].w;
        }
        #pragma unroll
        for (int os = 1; os <= 2; os <<= 1){
            slo += __shfl_xor_sync(0xffffffffu, slo, os);
            shi += __shfl_xor_sync(0xffffffffu, shi, os);
        }
        float mulo = slo * (1.0f / DH), muhi = shi * (1.0f / DH);
        float vlo = 0.f, vhi = 0.f;
        #pragma unroll
        for (int nt = 0; nt < 8; nt++){
            float a0 = ov[nt].x - mulo, a1 = ov[nt].y - mulo;
            float a2 = ov[nt].z - muhi, a3 = ov[nt].w - muhi;
            vlo += a0*a0 + a1*a1;  vhi += a2*a2 + a3*a3;
        }
        #pragma unroll
        for (int os = 1; os <= 2; os <<= 1){
            vlo += __shfl_xor_sync(0xffffffffu, vlo, os);
            vhi += __shfl_xor_sync(0xffffffffu, vhi, os);
        }
        float rslo = rsqrtf(vlo * (1.0f / DH) + LN_EPS);
        float rshi = rsqrtf(vhi * (1.0f / DH) + LN_EPS);

        int b_ = bh >> 2, h = bh & 3;
        int tok_lo = b_*TT + q0 + wq*16 + g;
        float* OdLo = g_O + (size_t)tok_lo*256 + h*DH;
        float* OdHi = OdLo + 8*256;
        #pragma unroll
        for (int nt = 0; nt < 8; nt++){
            float2 wv2 = *(const float2*)(hnw + nt*8 + 2*q);
            float2 bv2 = *(const float2*)(hnb + nt*8 + 2*q);
            float y0 = ((ov[nt].x - mulo)*rslo*wv2.x + bv2.x) * (1.0f - LAMBDA_INIT);
            float y1 = ((ov[nt].y - mulo)*rslo*wv2.y + bv2.y) * (1.0f - LAMBDA_INIT);
            float y2 = ((ov[nt].z - muhi)*rshi*wv2.x + bv2.x) * (1.0f - LAMBDA_INIT);
            float y3 = ((ov[nt].w - muhi)*rshi*wv2.y + bv2.y) * (1.0f - LAMBDA_INIT);
            *(float2*)(OdLo + nt*8 + 2*q) = make_float2(y0, y1);
            *(float2*)(OdHi + nt*8 + 2*q) = make_float2(y2, y3);
        }
    }
}

// ================= K3: output GEMM tf32 (16384 x 128 x 256) + residual =================
#define OUT_SAT (64*36)
#define OUT_SBT (32*136)
__global__ __launch_bounds__(256) void out_gemm(const float* __restrict__ wo,
                                                const float* __restrict__ tokens,
                                                float* __restrict__ out){
    extern __shared__ float dynsm[];
    float* sA = dynsm;                 // 2 stages [64][36]
    float* sB = dynsm + 2*OUT_SAT;     // 2 stages [32][136]

    int brow = blockIdx.x;             // 0..255
    int tid = threadIdx.x;
    int w = tid >> 5, lane = tid & 31, g = lane >> 2, q = lane & 3;
    int wm = w >> 2, wn = w & 3;
    float4 acc[2][4];
    #pragma unroll
    for (int i = 0; i < 2; i++)
        #pragma unroll
        for (int j = 0; j < 4; j++) acc[i][j] = make_float4(0.f,0.f,0.f,0.f);

    #pragma unroll
    for (int f = tid; f < 512; f += 256){
        int r = f >> 3, c4 = f & 7;
        cp16(sA + r*36 + c4*4, g_O + (size_t)(brow*64 + r)*256 + c4*4);
    }
    #pragma unroll
    for (int f = tid; f < 1024; f += 256){
        int kr = f >> 5, c4 = f & 31;
        cp16(sB + kr*136 + c4*4, wo + (size_t)kr*DD + c4*4);
    }
    CP_COMMIT;

    for (int kc = 0; kc < 8; kc++){
        if (kc + 1 < 8){
            float* dA = sA + ((kc+1)&1)*OUT_SAT;
            float* dB = sB + ((kc+1)&1)*OUT_SBT;
            #pragma unroll
            for (int f = tid; f < 512; f += 256){
                int r = f >> 3, c4 = f & 7;
                cp16(dA + r*36 + c4*4, g_O + (size_t)(brow*64 + r)*256 + (kc+1)*32 + c4*4);
            }
            #pragma unroll
            for (int f = tid; f < 1024; f += 256){
                int kr = f >> 5, c4 = f & 31;
                cp16(dB + kr*136 + c4*4, wo + (size_t)((kc+1)*32 + kr)*DD + c4*4);
            }
            CP_COMMIT;
            CP_WAIT1;
        } else {
            CP_WAIT0;
        }
        __syncthreads();
        const float* sAc = sA + (kc&1)*OUT_SAT;
        const float* sBc = sB + (kc&1)*OUT_SBT;
        #pragma unroll
        for (int ks = 0; ks < 4; ks++){
            uint32_t a[2][4];
            int kk = ks*8 + q;
            #pragma unroll
            for (int mt = 0; mt < 2; mt++){
                int r = wm*32 + mt*16 + g;
                a[mt][0] = __float_as_uint(sAc[r*36 + kk]);
                a[mt][1] = __float_as_uint(sAc[(r+8)*36 + kk]);
                a[mt][2] = __float_as_uint(sAc[r*36 + kk + 4]);
                a[mt][3] = __float_as_uint(sAc[(r+8)*36 + kk + 4]);
            }
            #pragma unroll
            for (int nt = 0; nt < 4; nt++){
                uint32_t b[2];
                int n = wn*32 + nt*8 + g;
                b[0] = __float_as_uint(sBc[kk*136 + n]);
                b[1] = __float_as_uint(sBc[(kk+4)*136 + n]);
                #pragma unroll
                for (int mt = 0; mt < 2; mt++)
                    mma8(acc[mt][nt], a[mt], b, acc[mt][nt]);
            }
        }
        __syncthreads();
    }

    #pragma unroll
    for (int mt = 0; mt < 2; mt++){
        int r0 = brow*64 + wm*32 + mt*16 + g;
        int r1 = r0 + 8;
        #pragma unroll
        for (int nt = 0; nt < 4; nt++){
            int col = wn*32 + nt*8 + 2*q;
            float2 t0 = *(const float2*)(tokens + (size_t)r0*DD + col);
            float2 t1 = *(const float2*)(tokens + (size_t)r1*DD + col);
            *(float2*)(out + (size_t)r0*DD + col) = make_float2(acc[mt][nt].x + t0.x, acc[mt][nt].y + t0.y);
            *(float2*)(out + (size_t)r1*DD + col) = make_float2(acc[mt][nt].z + t1.x, acc[mt][nt].w + t1.y);
        }
    }
}

// ================= launch =================
#define QKV_SMEM ((2*QKV_SAT + 2*QKV_SBT) * 4)
#define ATTN_SMEM ((OVR + 2*SKT + 2*SVT) * 4)
#define OUT_SMEM ((2*OUT_SAT + 2*OUT_SBT) * 4)

extern "C" void kernel_launch(void* const* d_in, const int* in_sizes, int n_in,
                              void* d_out, int out_size){
    const float* tokens = (const float*)d_in[0];
    const float* ln_w   = (const float*)d_in[1];
    const float* ln_b   = (const float*)d_in[2];
    const float* wq     = (const float*)d_in[3];
    const float* wk     = (const float*)d_in[4];
    const float* wv     = (const float*)d_in[5];
    const float* wo     = (const float*)d_in[6];
    const float* lq1    = (const float*)d_in[7];
    const float* lk1    = (const float*)d_in[8];
    const float* lq2    = (const float*)d_in[9];
    const float* lk2    = (const float*)d_in[10];
    const float* sig_s  = (const float*)d_in[11];
    const float* sig_n  = (const float*)d_in[12];
    const float* hnw    = (const float*)d_in[13];
    const float* hnb    = (const float*)d_in[14];
    float* out = (float*)d_out;

    static int attr_done = 0;
    if (!attr_done){
        cudaFuncSetAttribute(qkv_gemm, cudaFuncAttributeMaxDynamicSharedMemorySize, QKV_SMEM);
        cudaFuncSetAttribute(attn_kernel, cudaFuncAttributeMaxDynamicSharedMemorySize, ATTN_SMEM);
        cudaFuncSetAttribute(out_gemm, cudaFuncAttributeMaxDynamicSharedMemorySize, OUT_SMEM);
        attr_done = 1;
    }

    ln_kernel<<<NTOK/8, dim3(32,8)>>>(tokens, ln_w, ln_b);
    qkv_gemm<<<dim3(NTOK/128, 6), 256, QKV_SMEM>>>(wq, wk, wv);
    attn_kernel<<<dim3(TT/64, BB*HH), 256, ATTN_SMEM>>>(lq1, lk1, lq2, lk2, sig_s, sig_n, hnw, hnb);
    out_gemm<<<NTOK/64, 256, OUT_SMEM>>>(wo, tokens, out);
}

// round 11
// speedup vs baseline: 1.0195x; 1.0195x over previous
#include <cuda_runtime.h>
#include <cuda_bf16.h>
#include <math.h>
#include <stdint.h>

// ---------------- problem constants ----------------
#define BB 8
#define TT 2048
#define DD 128
#define HH 4
#define HD 32
#define DH 64
#define NTOK (BB*TT)
#define SCALE 0.17677669529663687f
#define LOG2E 1.4426950408889634f
#define LAMBDA_INIT 0.8f
#define LN_EPS 1e-5f
#define BAND 64

// ---------------- scratch ----------------
__device__ float g_xnorm[NTOK * DD];
__device__ float g_Q[BB*HH*TT*DH];
__device__ float g_K[BB*HH*TT*DH];
__device__ float g_V[BB*HH*TT*DH];
__device__ float g_O[NTOK * 256];

// ---------------- helpers ----------------
__device__ __forceinline__ uint32_t f2tf(float x){
    uint32_t r; asm("cvt.rna.tf32.f32 %0, %1;" : "=r"(r) : "f"(x)); return r;
}
__device__ __forceinline__ float tfr(float x){ return __uint_as_float(f2tf(x)); }

__device__ __forceinline__ void mma8(float4& d, const uint32_t* a, const uint32_t* b, const float4& c){
    asm volatile("mma.sync.aligned.m16n8k8.row.col.f32.tf32.tf32.f32 "
        "{%0,%1,%2,%3}, {%4,%5,%6,%7}, {%8,%9}, {%10,%11,%12,%13};"
        : "=f"(d.x),"=f"(d.y),"=f"(d.z),"=f"(d.w)
        : "r"(a[0]),"r"(a[1]),"r"(a[2]),"r"(a[3]),
          "r"(b[0]),"r"(b[1]),
          "f"(c.x),"f"(c.y),"f"(c.z),"f"(c.w));
}
__device__ __forceinline__ void cp16(float* smem, const float* gmem){
    uint32_t s = (uint32_t)__cvta_generic_to_shared(smem);
    asm volatile("cp.async.cg.shared.global [%0], [%1], 16;" :: "r"(s), "l"(gmem));
}
#define CP_COMMIT asm volatile("cp.async.commit_group;")
#define CP_WAIT0 asm volatile("cp.async.wait_group 0;")
#define CP_WAIT1 asm volatile("cp.async.wait_group 1;")
#define CP_WAIT2 asm volatile("cp.async.wait_group 2;")

// ================= K0: layernorm (tf32-rounded output) =================
__global__ __launch_bounds__(256) void ln_kernel(const float* __restrict__ x,
                                                 const float* __restrict__ w,
                                                 const float* __restrict__ b){
    int token = blockIdx.x * 8 + threadIdx.y;
    int lane  = threadIdx.x;
    const float4* xr = (const float4*)(x + (size_t)token * DD);
    float4 v = xr[lane];
    float s = v.x + v.y + v.z + v.w;
    #pragma unroll
    for (int o = 16; o; o >>= 1) s += __shfl_xor_sync(0xffffffffu, s, o);
    float mu = s * (1.0f / DD);
    float dx0 = v.x - mu, dx1 = v.y - mu, dx2 = v.z - mu, dx3 = v.w - mu;
    float sq = dx0*dx0 + dx1*dx1 + dx2*dx2 + dx3*dx3;
    #pragma unroll
    for (int o = 16; o; o >>= 1) sq += __shfl_xor_sync(0xffffffffu, sq, o);
    float rstd = rsqrtf(sq * (1.0f / DD) + LN_EPS);
    float4 wv = ((const float4*)w)[lane];
    float4 bv = ((const float4*)b)[lane];
    float4 out;
    out.x = tfr(dx0 * rstd * wv.x + bv.x);
    out.y = tfr(dx1 * rstd * wv.y + bv.y);
    out.z = tfr(dx2 * rstd * wv.z + bv.z);
    out.w = tfr(dx3 * rstd * wv.w + bv.w);
    ((float4*)(g_xnorm + (size_t)token * DD))[lane] = out;
}

// ================= K1: QKV GEMM tf32 (16384 x 768 x 128), 3-stage cp.async =================
#define QKV_SAT (128*36)
#define QKV_SBT (32*136)
__global__ __launch_bounds__(256) void qkv_gemm(const float* __restrict__ wq,
                                                const float* __restrict__ wk,
                                                const float* __restrict__ wv){
    extern __shared__ float dynsm[];
    float* sA = dynsm;                 // 3 stages [128][36]
    float* sB = dynsm + 3*QKV_SAT;     // 3 stages [32][136]

    int brow = blockIdx.x, bc = blockIdx.y;
    int tid = threadIdx.x;
    int w = tid >> 5, lane = tid & 31, g = lane >> 2, q = lane & 3;
    int wm = w >> 2, wn = w & 3;
    const float* W = (bc < 2) ? wq : (bc < 4 ? wk : wv);
    int colbase = (bc & 1) * 128;
    float4 acc[4][4];
    #pragma unroll
    for (int i = 0; i < 4; i++)
        #pragma unroll
        for (int j = 0; j < 4; j++) acc[i][j] = make_float4(0.f,0.f,0.f,0.f);

    // prologue: issue chunks 0 and 1
    #pragma unroll
    for (int pc = 0; pc < 2; pc++){
        float* dA = sA + pc*QKV_SAT;
        float* dB = sB + pc*QKV_SBT;
        #pragma unroll
        for (int f = tid; f < 1024; f += 256){
            int r = f >> 3, c4 = f & 7;
            cp16(dA + r*36 + c4*4, g_xnorm + (size_t)(brow*128 + r)*DD + pc*32 + c4*4);
        }
        #pragma unroll
        for (int f = tid; f < 1024; f += 256){
            int kr = f >> 5, c4 = f & 31;
            cp16(dB + kr*136 + c4*4, W + (size_t)(pc*32 + kr)*256 + colbase + c4*4);
        }
        CP_COMMIT;
    }

    for (int kc = 0; kc < 4; kc++){
        if (kc + 2 < 4){
            int st = (kc + 2) % 3;
            float* dA = sA + st*QKV_SAT;
            float* dB = sB + st*QKV_SBT;
            #pragma unroll
            for (int f = tid; f < 1024; f += 256){
                int r = f >> 3, c4 = f & 7;
                cp16(dA + r*36 + c4*4, g_xnorm + (size_t)(brow*128 + r)*DD + (kc+2)*32 + c4*4);
            }
            #pragma unroll
            for (int f = tid; f < 1024; f += 256){
                int kr = f >> 5, c4 = f & 31;
                cp16(dB + kr*136 + c4*4, W + (size_t)((kc+2)*32 + kr)*256 + colbase + c4*4);
            }
            CP_COMMIT;
            CP_WAIT2;
        } else if (kc + 1 < 4){
            CP_WAIT1;
        } else {
            CP_WAIT0;
        }
        __syncthreads();
        const float* sAc = sA + (kc%3)*QKV_SAT;
        const float* sBc = sB + (kc%3)*QKV_SBT;
        #pragma unroll
        for (int ks = 0; ks < 4; ks++){
            uint32_t a[4][4];
            int kk = ks*8 + q;
            #pragma unroll
            for (int mt = 0; mt < 4; mt++){
                int r = wm*64 + mt*16 + g;
                a[mt][0] = __float_as_uint(sAc[r*36 + kk]);
                a[mt][1] = __float_as_uint(sAc[(r+8)*36 + kk]);
                a[mt][2] = __float_as_uint(sAc[r*36 + kk + 4]);
                a[mt][3] = __float_as_uint(sAc[(r+8)*36 + kk + 4]);
            }
            #pragma unroll
            for (int nt = 0; nt < 4; nt++){
                uint32_t b[2];
                int n = wn*32 + nt*8 + g;
                b[0] = __float_as_uint(sBc[kk*136 + n]);
                b[1] = __float_as_uint(sBc[(kk+4)*136 + n]);
                #pragma unroll
                for (int mt = 0; mt < 4; mt++)
                    mma8(acc[mt][nt], a[mt], b, acc[mt][nt]);
            }
        }
        __syncthreads();
    }

    int mat = bc >> 1;
    float* dst = (mat == 0) ? g_Q : (mat == 1 ? g_K : g_V);
    #pragma unroll
    for (int mt = 0; mt < 4; mt++){
        int r0 = brow*128 + wm*64 + mt*16 + g;
        int r1 = r0 + 8;
        int b0_ = r0 >> 11, t0 = r0 & (TT-1);
        int b1_ = r1 >> 11, t1 = r1 & (TT-1);
        #pragma unroll
        for (int nt = 0; nt < 4; nt++){
            int col = colbase + wn*32 + nt*8 + 2*q;
            int head = col >> 6, dim = col & 63;
            float* p0 = dst + ((size_t)((b0_*HH + head)*TT + t0))*DH + dim;
            float* p1 = dst + ((size_t)((b1_*HH + head)*TT + t1))*DH + dim;
            *(float2*)p0 = make_float2(tfr(acc[mt][nt].x), tfr(acc[mt][nt].y));
            *(float2*)p1 = make_float2(tfr(acc[mt][nt].z), tfr(acc[mt][nt].w));
        }
    }
}

// ================= K2: branch-parallel banded attention (R9 config: KTILE=64) =================
#define SKT (64*68)
#define SVT (64*72)
#define SPW (16*36)
__global__ __launch_bounds__(256) void attn_kernel(
        const float* __restrict__ lq1, const float* __restrict__ lk1,
        const float* __restrict__ lq2, const float* __restrict__ lk2,
        const float* __restrict__ sig_s_p, const float* __restrict__ sig_n_p,
        const float* __restrict__ hnw, const float* __restrict__ hnb){
    extern __shared__ float dynsm[];
    float* sQ = dynsm;              // [64][68]
    float* sK = dynsm + 64*68;      // 2 stages [64 keys][68]
    float* sV = sK + 2*SKT;         // 2 stages [64 keys][72]
    float* sPb = sV + 2*SVT;        // 8 warps x [16][36]; reused as combine buf [64][72]

    int bh = blockIdx.y;
    int q0 = blockIdx.x * 64;
    int tid = threadIdx.x;
    int w = tid >> 5, lane = tid & 31, g = lane >> 2, q = lane & 3;
    int bw = w & 1, wq = w >> 1;
    float* sP = sPb + w*SPW;

    const float* Qb = g_Q + (size_t)bh * TT * DH;
    const float* Kb = g_K + (size_t)bh * TT * DH;
    const float* Vb = g_V + (size_t)bh * TT * DH;

    int klo = q0 - BAND; if (klo < 0) klo = 0;
    int khi = q0 + 64 + BAND; if (khi > TT) khi = TT;
    int ntile = (khi - klo) >> 6;

    #pragma unroll
    for (int f = tid; f < 1024; f += 256){
        int r = f >> 4, c4 = f & 15;
        cp16(sQ + r*68 + c4*4, Qb + (size_t)(q0 + r)*DH + c4*4);
    }
    CP_COMMIT;
    #pragma unroll
    for (int f = tid; f < 1024; f += 256){
        int kk = f >> 4, c4 = f & 15;
        cp16(sK + kk*68 + c4*4, Kb + (size_t)(klo + kk)*DH + c4*4);
        cp16(sV + kk*72 + c4*4, Vb + (size_t)(klo + kk)*DH + c4*4);
    }
    CP_COMMIT;

    float e1 = 0.f, e2 = 0.f;
    #pragma unroll
    for (int i = 0; i < HD; i++){ e1 += lq1[i]*lk1[i]; e2 += lq2[i]*lk2[i]; }
    float lam = __expf(e1) - __expf(e2) + LAMBDA_INIT;
    float sig_s = fmaxf(sig_s_p[0], 1.0f), sig_n = fmaxf(sig_n_p[0], 1.0f);
    float sc2 = SCALE * LOG2E;
    float cb = bw ? (-0.5f * LOG2E / (sig_n * sig_n))
                  : (-0.5f * LOG2E / (sig_s * sig_s));

    CP_WAIT1;
    __syncthreads();

    uint32_t qa[4][4];
    {
        int rb = (wq*16 + g)*68 + bw*32;
        #pragma unroll
        for (int ks = 0; ks < 4; ks++){
            int d0 = ks*8 + q;
            qa[ks][0] = __float_as_uint(sQ[rb + d0]);
            qa[ks][1] = __float_as_uint(sQ[rb + 8*68 + d0]);
            qa[ks][2] = __float_as_uint(sQ[rb + d0 + 4]);
            qa[ks][3] = __float_as_uint(sQ[rb + 8*68 + d0 + 4]);
        }
    }

    float4 o[8];
    #pragma unroll
    for (int nt = 0; nt < 8; nt++) o[nt] = make_float4(0.f,0.f,0.f,0.f);
    float l_lo = 0.f, l_hi = 0.f;

    float row_lo = (float)(q0 + wq*16 + g);
    float row_hi = row_lo + 8.0f;

    for (int it = 0; it < ntile; it++){
        int ksb = klo + it*64;
        if (it + 1 < ntile){
            float* dK = sK + ((it+1)&1)*SKT;
            float* dV = sV + ((it+1)&1)*SVT;
            int kn = klo + (it+1)*64;
            #pragma unroll
            for (int f = tid; f < 1024; f += 256){
                int kk = f >> 4, c4 = f & 15;
                cp16(dK + kk*68 + c4*4, Kb + (size_t)(kn + kk)*DH + c4*4);
                cp16(dV + kk*72 + c4*4, Vb + (size_t)(kn + kk)*DH + c4*4);
            }
            CP_COMMIT;
            CP_WAIT1;
        } else {
            CP_WAIT0;
        }
        __syncthreads();
        const float* sKc = sK + (it&1)*SKT;
        const float* sVc = sV + (it&1)*SVT;

        // ---- scores over 64 keys (this warp's branch only) ----
        float4 s[8];
        #pragma unroll
        for (int nt = 0; nt < 8; nt++) s[nt] = make_float4(0.f,0.f,0.f,0.f);
        #pragma unroll
        for (int ks = 0; ks < 4; ks++){
            int d0 = ks*8 + q + bw*32;
            #pragma unroll
            for (int nt = 0; nt < 8; nt++){
                uint32_t b[2];
                int kb = (nt*8 + g)*68 + d0;
                b[0] = __float_as_uint(sKc[kb]);
                b[1] = __float_as_uint(sKc[kb + 4]);
                mma8(s[nt], qa[ks], b, s[nt]);
            }
        }

        // ---- bias + exp (fixed reference), two 32-key halves for P/PV ----
        #pragma unroll
        for (int half = 0; half < 2; half++){
            #pragma unroll
            for (int nth = 0; nth < 4; nth++){
                int nt = half*4 + nth;
                float k0f = (float)(ksb + nt*8 + 2*q);
                float rx_lo = k0f - row_lo,  ry_lo = k0f + 1.0f - row_lo;
                float rx_hi = k0f - row_hi,  ry_hi = k0f + 1.0f - row_hi;
                float ax = exp2f(s[nt].x*sc2 + rx_lo*rx_lo*cb);
                float ay = exp2f(s[nt].y*sc2 + ry_lo*ry_lo*cb);
                float az = exp2f(s[nt].z*sc2 + rx_hi*rx_hi*cb);
                float aw = exp2f(s[nt].w*sc2 + ry_hi*ry_hi*cb);
                l_lo += ax + ay;  l_hi += az + aw;
                *(float2*)(sP + g*36 + nth*8 + 2*q)     = make_float2(ax, ay);
                *(float2*)(sP + (g+8)*36 + nth*8 + 2*q) = make_float2(az, aw);
            }
            __syncwarp();
            #pragma unroll
            for (int ks = 0; ks < 4; ks++){
                uint32_t a[4];
                int pk = ks*8 + q;
                a[0] = __float_as_uint(sP[g*36 + pk]);
                a[1] = __float_as_uint(sP[(g+8)*36 + pk]);
                a[2] = __float_as_uint(sP[g*36 + pk + 4]);
                a[3] = __float_as_uint(sP[(g+8)*36 + pk + 4]);
                int kv = half*32 + ks*8 + q;
                #pragma unroll
                for (int nt = 0; nt < 8; nt++){
                    uint32_t b[2];
                    b[0] = __float_as_uint(sVc[kv*72 + nt*8 + g]);
                    b[1] = __float_as_uint(sVc[(kv+4)*72 + nt*8 + g]);
                    mma8(o[nt], a, b, o[nt]);
                }
            }
            __syncwarp();
        }
        __syncthreads();
    }

    // ---- reduce l over quad ----
    #pragma unroll
    for (int os = 1; os <= 2; os <<= 1){
        l_lo += __shfl_xor_sync(0xffffffffu, l_lo, os);
        l_hi += __shfl_xor_sync(0xffffffffu, l_hi, os);
    }

    // ---- branch combine via smem (sPb reused as [64][72] float buffer) ----
    if (bw == 1){
        float s_lo = lam / l_lo, s_hi = lam / l_hi;
        int rb0 = (wq*16 + g)*72, rb1 = (wq*16 + g + 8)*72;
        #pragma unroll
        for (int nt = 0; nt < 8; nt++){
            *(float2*)(sPb + rb0 + nt*8 + 2*q) = make_float2(o[nt].x*s_lo, o[nt].y*s_lo);
            *(float2*)(sPb + rb1 + nt*8 + 2*q) = make_float2(o[nt].z*s_hi, o[nt].w*s_hi);
        }
    }
    __syncthreads();
    if (bw == 0){
        float i_lo = 1.0f / l_lo, i_hi = 1.0f / l_hi;
        int rb0 = (wq*16 + g)*72, rb1 = (wq*16 + g + 8)*72;
        float4 ov[8];
        float slo = 0.f, shi = 0.f;
        #pragma unroll
        for (int nt = 0; nt < 8; nt++){
            float2 c0 = *(const float2*)(sPb + rb0 + nt*8 + 2*q);
            float2 c1 = *(const float2*)(sPb + rb1 + nt*8 + 2*q);
            ov[nt].x = o[nt].x*i_lo - c0.x;
            ov[nt].y = o[nt].y*i_lo - c0.y;
            ov[nt].z = o[nt].z*i_hi - c1.x;
            ov[nt].w = o[nt].w*i_hi - c1.y;
            slo += ov[nt].x + ov[nt].y;
            shi += ov[nt].z + ov[nt].w;
        }
        #pragma unroll
        for (int os = 1; os <= 2; os <<= 1){
            slo += __shfl_xor_sync(0xffffffffu, slo, os);
            shi += __shfl_xor_sync(0xffffffffu, shi, os);
        }
        float mulo = slo * (1.0f / DH), muhi = shi * (1.0f / DH);
        float vlo = 0.f, vhi = 0.f;
        #pragma unroll
        for (int nt = 0; nt < 8; nt++){
            float a0 = ov[nt].x - mulo, a1 = ov[nt].y - mulo;
            float a2 = ov[nt].z - muhi, a3 = ov[nt].w - muhi;
            vlo += a0*a0 + a1*a1;  vhi += a2*a2 + a3*a3;
        }
        #pragma unroll
        for (int os = 1; os <= 2; os <<= 1){
            vlo += __shfl_xor_sync(0xffffffffu, vlo, os);
            vhi += __shfl_xor_sync(0xffffffffu, vhi, os);
        }
        float rslo = rsqrtf(vlo * (1.0f / DH) + LN_EPS);
        float rshi = rsqrtf(vhi * (1.0f / DH) + LN_EPS);

        int b_ = bh >> 2, h = bh & 3;
        int tok_lo = b_*TT + q0 + wq*16 + g;
        float* OdLo = g_O + (size_t)tok_lo*256 + h*DH;
        float* OdHi = OdLo + 8*256;
        #pragma unroll
        for (int nt = 0; nt < 8; nt++){
            float2 wv2 = *(const float2*)(hnw + nt*8 + 2*q);
            float2 bv2 = *(const float2*)(hnb + nt*8 + 2*q);
            float y0 = ((ov[nt].x - mulo)*rslo*wv2.x + bv2.x) * (1.0f - LAMBDA_INIT);
            float y1 = ((ov[nt].y - mulo)*rslo*wv2.y + bv2.y) * (1.0f - LAMBDA_INIT);
            float y2 = ((ov[nt].z - muhi)*rshi*wv2.x + bv2.x) * (1.0f - LAMBDA_INIT);
            float y3 = ((ov[nt].w - muhi)*rshi*wv2.y + bv2.y) * (1.0f - LAMBDA_INIT);
            *(float2*)(OdLo + nt*8 + 2*q) = make_float2(y0, y1);
            *(float2*)(OdHi + nt*8 + 2*q) = make_float2(y2, y3);
        }
    }
}

// ================= K3: output GEMM tf32 (16384 x 128 x 256) + residual, 3-stage =================
#define OUT_SAT (64*36)
#define OUT_SBT (32*136)
__global__ __launch_bounds__(256) void out_gemm(const float* __restrict__ wo,
                                                const float* __restrict__ tokens,
                                                float* __restrict__ out){
    extern __shared__ float dynsm[];
    float* sA = dynsm;                 // 3 stages [64][36]
    float* sB = dynsm + 3*OUT_SAT;     // 3 stages [32][136]

    int brow = blockIdx.x;             // 0..255
    int tid = threadIdx.x;
    int w = tid >> 5, lane = tid & 31, g = lane >> 2, q = lane & 3;
    int wm = w >> 2, wn = w & 3;
    float4 acc[2][4];
    #pragma unroll
    for (int i = 0; i < 2; i++)
        #pragma unroll
        for (int j = 0; j < 4; j++) acc[i][j] = make_float4(0.f,0.f,0.f,0.f);

    // prologue: issue chunks 0 and 1
    #pragma unroll
    for (int pc = 0; pc < 2; pc++){
        float* dA = sA + pc*OUT_SAT;
        float* dB = sB + pc*OUT_SBT;
        #pragma unroll
        for (int f = tid; f < 512; f += 256){
            int r = f >> 3, c4 = f & 7;
            cp16(dA + r*36 + c4*4, g_O + (size_t)(brow*64 + r)*256 + pc*32 + c4*4);
        }
        #pragma unroll
        for (int f = tid; f < 1024; f += 256){
            int kr = f >> 5, c4 = f & 31;
            cp16(dB + kr*136 + c4*4, wo + (size_t)(pc*32 + kr)*DD + c4*4);
        }
        CP_COMMIT;
    }

    for (int kc = 0; kc < 8; kc++){
        if (kc + 2 < 8){
            int st = (kc + 2) % 3;
            float* dA = sA + st*OUT_SAT;
            float* dB = sB + st*OUT_SBT;
            #pragma unroll
            for (int f = tid; f < 512; f += 256){
                int r = f >> 3, c4 = f & 7;
                cp16(dA + r*36 + c4*4, g_O + (size_t)(brow*64 + r)*256 + (kc+2)*32 + c4*4);
            }
            #pragma unroll
            for (int f = tid; f < 1024; f += 256){
                int kr = f >> 5, c4 = f & 31;
                cp16(dB + kr*136 + c4*4, wo + (size_t)((kc+2)*32 + kr)*DD + c4*4);
            }
            CP_COMMIT;
            CP_WAIT2;
        } else if (kc + 1 < 8){
            CP_WAIT1;
        } else {
            CP_WAIT0;
        }
        __syncthreads();
        const float* sAc = sA + (kc%3)*OUT_SAT;
        const float* sBc = sB + (kc%3)*OUT_SBT;
        #pragma unroll
        for (int ks = 0; ks < 4; ks++){
            uint32_t a[2][4];
            int kk = ks*8 + q;
            #pragma unroll
            for (int mt = 0; mt < 2; mt++){
                int r = wm*32 + mt*16 + g;
                a[mt][0] = __float_as_uint(sAc[r*36 + kk]);
                a[mt][1] = __float_as_uint(sAc[(r+8)*36 + kk]);
                a[mt][2] = __float_as_uint(sAc[r*36 + kk + 4]);
                a[mt][3] = __float_as_uint(sAc[(r+8)*36 + kk + 4]);
            }
            #pragma unroll
            for (int nt = 0; nt < 4; nt++){
                uint32_t b[2];
                int n = wn*32 + nt*8 + g;
                b[0] = __float_as_uint(sBc[kk*136 + n]);
                b[1] = __float_as_uint(sBc[(kk+4)*136 + n]);
                #pragma unroll
                for (int mt = 0; mt < 2; mt++)
                    mma8(acc[mt][nt], a[mt], b, acc[mt][nt]);
            }
        }
        __syncthreads();
    }

    #pragma unroll
    for (int mt = 0; mt < 2; mt++){
        int r0 = brow*64 + wm*32 + mt*16 + g;
        int r1 = r0 + 8;
        #pragma unroll
        for (int nt = 0; nt < 4; nt++){
            int col = wn*32 + nt*8 + 2*q;
            float2 t0 = *(const float2*)(tokens + (size_t)r0*DD + col);
            float2 t1 = *(const float2*)(tokens + (size_t)r1*DD + col);
            *(float2*)(out + (size_t)r0*DD + col) = make_float2(acc[mt][nt].x + t0.x, acc[mt][nt].y + t0.y);
            *(float2*)(out + (size_t)r1*DD + col) = make_float2(acc[mt][nt].z + t1.x, acc[mt][nt].w + t1.y);
        }
    }
}

// ================= launch =================
#define QKV_SMEM ((3*QKV_SAT + 3*QKV_SBT) * 4)
#define ATTN_SMEM ((64*68 + 2*SKT + 2*SVT + 8*SPW) * 4)
#define OUT_SMEM ((3*OUT_SAT + 3*OUT_SBT) * 4)

extern "C" void kernel_launch(void* const* d_in, const int* in_sizes, int n_in,
                              void* d_out, int out_size){
    const float* tokens = (const float*)d_in[0];
    const float* ln_w   = (const float*)d_in[1];
    const float* ln_b   = (const float*)d_in[2];
    const float* wq     = (const float*)d_in[3];
    const float* wk     = (const float*)d_in[4];
    const float* wv     = (const float*)d_in[5];
    const float* wo     = (const float*)d_in[6];
    const float* lq1    = (const float*)d_in[7];
    const float* lk1    = (const float*)d_in[8];
    const float* lq2    = (const float*)d_in[9];
    const float* lk2    = (const float*)d_in[10];
    const float* sig_s  = (const float*)d_in[11];
    const float* sig_n  = (const float*)d_in[12];
    const float* hnw    = (const float*)d_in[13];
    const float* hnb    = (const float*)d_in[14];
    float* out = (float*)d_out;

    static int attr_done = 0;
    if (!attr_done){
        cudaFuncSetAttribute(qkv_gemm, cudaFuncAttributeMaxDynamicSharedMemorySize, QKV_SMEM);
        cudaFuncSetAttribute(attn_kernel, cudaFuncAttributeMaxDynamicSharedMemorySize, ATTN_SMEM);
        cudaFuncSetAttribute(out_gemm, cudaFuncAttributeMaxDynamicSharedMemorySize, OUT_SMEM);
        attr_done = 1;
    }

    ln_kernel<<<NTOK/8, dim3(32,8)>>>(tokens, ln_w, ln_b);
    qkv_gemm<<<dim3(NTOK/128, 6), 256, QKV_SMEM>>>(wq, wk, wv);
    attn_kernel<<<dim3(TT/64, BB*HH), 256, ATTN_SMEM>>>(lq1, lk1, lq2, lk2, sig_s, sig_n, hnw, hnb);
    out_gemm<<<NTOK/64, 256, OUT_SMEM>>>(wo, tokens, out);
}

// round 12
// speedup vs baseline: 1.1782x; 1.1556x over previous
#include <cuda_runtime.h>
#include <cuda_bf16.h>
#include <math.h>
#include <stdint.h>

// ---------------- problem constants ----------------
#define BB 8
#define TT 2048
#define DD 128
#define HH 4
#define HD 32
#define DH 64
#define NTOK (BB*TT)
#define SCALE 0.17677669529663687f
#define LOG2E 1.4426950408889634f
#define LAMBDA_INIT 0.8f
#define LN_EPS 1e-5f
#define BAND 64

// ---------------- scratch ----------------
__device__ float g_xnorm[NTOK * DD];
__device__ __nv_bfloat16 g_Qh[BB*HH*TT*DH];   // [bh][t][64]
__device__ __nv_bfloat16 g_Kh[BB*HH*TT*DH];   // [bh][t][64]
__device__ __nv_bfloat16 g_Vt[BB*HH*DH*TT];   // [bh][dim][t]  (transposed)
__device__ float g_O[NTOK * 256];

// ---------------- helpers ----------------
__device__ __forceinline__ uint32_t f2tf(float x){
    uint32_t r; asm("cvt.rna.tf32.f32 %0, %1;" : "=r"(r) : "f"(x)); return r;
}
__device__ __forceinline__ float tfr(float x){ return __uint_as_float(f2tf(x)); }

__device__ __forceinline__ void mma8(float4& d, const uint32_t* a, const uint32_t* b, const float4& c){
    asm volatile("mma.sync.aligned.m16n8k8.row.col.f32.tf32.tf32.f32 "
        "{%0,%1,%2,%3}, {%4,%5,%6,%7}, {%8,%9}, {%10,%11,%12,%13};"
        : "=f"(d.x),"=f"(d.y),"=f"(d.z),"=f"(d.w)
        : "r"(a[0]),"r"(a[1]),"r"(a[2]),"r"(a[3]),
          "r"(b[0]),"r"(b[1]),
          "f"(c.x),"f"(c.y),"f"(c.z),"f"(c.w));
}
__device__ __forceinline__ void mma16bf(float4& d, const uint32_t* a, const uint32_t* b, const float4& c){
    asm volatile("mma.sync.aligned.m16n8k16.row.col.f32.bf16.bf16.f32 "
        "{%0,%1,%2,%3}, {%4,%5,%6,%7}, {%8,%9}, {%10,%11,%12,%13};"
        : "=f"(d.x),"=f"(d.y),"=f"(d.z),"=f"(d.w)
        : "r"(a[0]),"r"(a[1]),"r"(a[2]),"r"(a[3]),
          "r"(b[0]),"r"(b[1]),
          "f"(c.x),"f"(c.y),"f"(c.z),"f"(c.w));
}
__device__ __forceinline__ void cp16(void* smem, const void* gmem){
    uint32_t s = (uint32_t)__cvta_generic_to_shared(smem);
    asm volatile("cp.async.cg.shared.global [%0], [%1], 16;" :: "r"(s), "l"(gmem));
}
#define CP_COMMIT asm volatile("cp.async.commit_group;")
#define CP_WAIT0 asm volatile("cp.async.wait_group 0;")
#define CP_WAIT1 asm volatile("cp.async.wait_group 1;")
#define CP_WAIT2 asm volatile("cp.async.wait_group 2;")

// ================= K0: layernorm (tf32-rounded output) =================
__global__ __launch_bounds__(256) void ln_kernel(const float* __restrict__ x,
                                                 const float* __restrict__ w,
                                                 const float* __restrict__ b){
    int token = blockIdx.x * 8 + threadIdx.y;
    int lane  = threadIdx.x;
    const float4* xr = (const float4*)(x + (size_t)token * DD);
    float4 v = xr[lane];
    float s = v.x + v.y + v.z + v.w;
    #pragma unroll
    for (int o = 16; o; o >>= 1) s += __shfl_xor_sync(0xffffffffu, s, o);
    float mu = s * (1.0f / DD);
    float dx0 = v.x - mu, dx1 = v.y - mu, dx2 = v.z - mu, dx3 = v.w - mu;
    float sq = dx0*dx0 + dx1*dx1 + dx2*dx2 + dx3*dx3;
    #pragma unroll
    for (int o = 16; o; o >>= 1) sq += __shfl_xor_sync(0xffffffffu, sq, o);
    float rstd = rsqrtf(sq * (1.0f / DD) + LN_EPS);
    float4 wv = ((const float4*)w)[lane];
    float4 bv = ((const float4*)b)[lane];
    float4 out;
    out.x = tfr(dx0 * rstd * wv.x + bv.x);
    out.y = tfr(dx1 * rstd * wv.y + bv.y);
    out.z = tfr(dx2 * rstd * wv.z + bv.z);
    out.w = tfr(dx3 * rstd * wv.w + bv.w);
    ((float4*)(g_xnorm + (size_t)token * DD))[lane] = out;
}

// ================= K1: QKV GEMM tf32, epilogue -> bf16 Q/K and bf16 V^T =================
#define QKV_SAT (128*36)
#define QKV_SBT (32*136)
__global__ __launch_bounds__(256) void qkv_gemm(const float* __restrict__ wq,
                                                const float* __restrict__ wk,
                                                const float* __restrict__ wv){
    extern __shared__ float dynsm[];
    float* sA = dynsm;                 // 3 stages [128][36]
    float* sB = dynsm + 3*QKV_SAT;     // 3 stages [32][136]

    int brow = blockIdx.x, bc = blockIdx.y;
    int tid = threadIdx.x;
    int w = tid >> 5, lane = tid & 31, g = lane >> 2, q = lane & 3;
    int wm = w >> 2, wn = w & 3;
    const float* W = (bc < 2) ? wq : (bc < 4 ? wk : wv);
    int colbase = (bc & 1) * 128;
    float4 acc[4][4];
    #pragma unroll
    for (int i = 0; i < 4; i++)
        #pragma unroll
        for (int j = 0; j < 4; j++) acc[i][j] = make_float4(0.f,0.f,0.f,0.f);

    #pragma unroll
    for (int pc = 0; pc < 2; pc++){
        float* dA = sA + pc*QKV_SAT;
        float* dB = sB + pc*QKV_SBT;
        #pragma unroll
        for (int f = tid; f < 1024; f += 256){
            int r = f >> 3, c4 = f & 7;
            cp16(dA + r*36 + c4*4, g_xnorm + (size_t)(brow*128 + r)*DD + pc*32 + c4*4);
        }
        #pragma unroll
        for (int f = tid; f < 1024; f += 256){
            int kr = f >> 5, c4 = f & 31;
            cp16(dB + kr*136 + c4*4, W + (size_t)(pc*32 + kr)*256 + colbase + c4*4);
        }
        CP_COMMIT;
    }

    for (int kc = 0; kc < 4; kc++){
        if (kc + 2 < 4){
            int st = (kc + 2) % 3;
            float* dA = sA + st*QKV_SAT;
            float* dB = sB + st*QKV_SBT;
            #pragma unroll
            for (int f = tid; f < 1024; f += 256){
                int r = f >> 3, c4 = f & 7;
                cp16(dA + r*36 + c4*4, g_xnorm + (size_t)(brow*128 + r)*DD + (kc+2)*32 + c4*4);
            }
            #pragma unroll
            for (int f = tid; f < 1024; f += 256){
                int kr = f >> 5, c4 = f & 31;
                cp16(dB + kr*136 + c4*4, W + (size_t)((kc+2)*32 + kr)*256 + colbase + c4*4);
            }
            CP_COMMIT;
            CP_WAIT2;
        } else if (kc + 1 < 4){
            CP_WAIT1;
        } else {
            CP_WAIT0;
        }
        __syncthreads();
        const float* sAc = sA + (kc%3)*QKV_SAT;
        const float* sBc = sB + (kc%3)*QKV_SBT;
        #pragma unroll
        for (int ks = 0; ks < 4; ks++){
            uint32_t a[4][4];
            int kk = ks*8 + q;
            #pragma unroll
            for (int mt = 0; mt < 4; mt++){
                int r = wm*64 + mt*16 + g;
                a[mt][0] = __float_as_uint(sAc[r*36 + kk]);
                a[mt][1] = __float_as_uint(sAc[(r+8)*36 + kk]);
                a[mt][2] = __float_as_uint(sAc[r*36 + kk + 4]);
                a[mt][3] = __float_as_uint(sAc[(r+8)*36 + kk + 4]);
            }
            #pragma unroll
            for (int nt = 0; nt < 4; nt++){
                uint32_t b[2];
                int n = wn*32 + nt*8 + g;
                b[0] = __float_as_uint(sBc[kk*136 + n]);
                b[1] = __float_as_uint(sBc[(kk+4)*136 + n]);
                #pragma unroll
                for (int mt = 0; mt < 4; mt++)
                    mma8(acc[mt][nt], a[mt], b, acc[mt][nt]);
            }
        }
        __syncthreads();
    }

    int mat = bc >> 1;
    #pragma unroll
    for (int mt = 0; mt < 4; mt++){
        int r0 = brow*128 + wm*64 + mt*16 + g;
        int r1 = r0 + 8;
        int b0_ = r0 >> 11, t0 = r0 & (TT-1);
        int b1_ = r1 >> 11, t1 = r1 & (TT-1);
        #pragma unroll
        for (int nt = 0; nt < 4; nt++){
            int col = colbase + wn*32 + nt*8 + 2*q;
            int head = col >> 6, dim = col & 63;
            if (mat < 2){
                __nv_bfloat16* dst = (mat == 0) ? g_Qh : g_Kh;
                __nv_bfloat162 h0 = __floats2bfloat162_rn(acc[mt][nt].x, acc[mt][nt].y);
                __nv_bfloat162 h1 = __floats2bfloat162_rn(acc[mt][nt].z, acc[mt][nt].w);
                *(__nv_bfloat162*)(dst + ((size_t)((b0_*HH + head)*TT + t0))*DH + dim) = h0;
                *(__nv_bfloat162*)(dst + ((size_t)((b1_*HH + head)*TT + t1))*DH + dim) = h1;
            } else {
                // V transposed: [bh][dim][t]
                size_t base0 = ((size_t)(b0_*HH + head)*DH + dim)*TT;
                size_t base1 = ((size_t)(b1_*HH + head)*DH + dim)*TT;
                g_Vt[base0 + t0]      = __float2bfloat16(acc[mt][nt].x);
                g_Vt[base0 + TT + t0] = __float2bfloat16(acc[mt][nt].y);
                g_Vt[base1 + t1]      = __float2bfloat16(acc[mt][nt].z);
                g_Vt[base1 + TT + t1] = __float2bfloat16(acc[mt][nt].w);
            }
        }
    }
}

// ================= K2: bf16 branch-parallel banded attention, KTILE=64 =================
// strides in bf16 elements: Q/K/Vt tiles 88 (16B-aligned rows, conflict-free), P 72.
#define QS 88
#define SKH (64*QS)
#define SVH (64*QS)
#define SPH (16*72)
__global__ __launch_bounds__(256) void attn_kernel(
        const float* __restrict__ lq1, const float* __restrict__ lk1,
        const float* __restrict__ lq2, const float* __restrict__ lk2,
        const float* __restrict__ sig_s_p, const float* __restrict__ sig_n_p,
        const float* __restrict__ hnw, const float* __restrict__ hnb){
    extern __shared__ __align__(16) char dynraw[];
    __nv_bfloat16* sQ  = (__nv_bfloat16*)dynraw;            // [64][88]
    __nv_bfloat16* sK  = sQ + 64*QS;                        // 2 stages [64 keys][88 dims]
    __nv_bfloat16* sVt = sK + 2*SKH;                        // 2 stages [64 dims][88 keys]
    __nv_bfloat16* sPb = sVt + 2*SVH;                       // 8 x [16][72]; overlay: combine [64][72] fp32

    int bh = blockIdx.y;
    int q0 = blockIdx.x * 64;
    int tid = threadIdx.x;
    int w = tid >> 5, lane = tid & 31, g = lane >> 2, q = lane & 3;
    int bw = w & 1, wq = w >> 1;
    __nv_bfloat16* sP = sPb + w*SPH;

    const __nv_bfloat16* Qb = g_Qh + (size_t)bh * TT * DH;
    const __nv_bfloat16* Kb = g_Kh + (size_t)bh * TT * DH;
    const __nv_bfloat16* Vt = g_Vt + (size_t)bh * DH * TT;

    int klo = q0 - BAND; if (klo < 0) klo = 0;
    int khi = q0 + 64 + BAND; if (khi > TT) khi = TT;
    int ntile = (khi - klo) >> 6;

    // G0: Q tile (64 rows x 64 dims bf16, 8 cp16/row)
    #pragma unroll
    for (int f = tid; f < 512; f += 256){
        int r = f >> 3, c8 = f & 7;
        cp16(sQ + r*QS + c8*8, Qb + (size_t)(q0 + r)*DH + c8*8);
    }
    CP_COMMIT;
    // G1: first K + V^T tiles
    #pragma unroll
    for (int f = tid; f < 512; f += 256){
        int kk = f >> 3, c8 = f & 7;
        cp16(sK + kk*QS + c8*8, Kb + (size_t)(klo + kk)*DH + c8*8);
        cp16(sVt + kk*QS + c8*8, Vt + (size_t)kk*TT + klo + c8*8);
    }
    CP_COMMIT;

    float e1 = 0.f, e2 = 0.f;
    #pragma unroll
    for (int i = 0; i < HD; i++){ e1 += lq1[i]*lk1[i]; e2 += lq2[i]*lk2[i]; }
    float lam = __expf(e1) - __expf(e2) + LAMBDA_INIT;
    float sig_s = fmaxf(sig_s_p[0], 1.0f), sig_n = fmaxf(sig_n_p[0], 1.0f);
    float sc2 = SCALE * LOG2E;
    float cb = bw ? (-0.5f * LOG2E / (sig_n * sig_n))
                  : (-0.5f * LOG2E / (sig_s * sig_s));

    CP_WAIT1;   // sQ ready
    __syncthreads();

    // preload Q a-frags (bf16, k-extent 32 = 2 k16-steps)
    uint32_t qa[2][4];
    {
        int rb = (wq*16 + g)*QS + bw*32;
        #pragma unroll
        for (int ks = 0; ks < 2; ks++){
            int d0 = ks*16 + 2*q;
            qa[ks][0] = *(const uint32_t*)(sQ + rb + d0);
            qa[ks][1] = *(const uint32_t*)(sQ + rb + 8*QS + d0);
            qa[ks][2] = *(const uint32_t*)(sQ + rb + d0 + 8);
            qa[ks][3] = *(const uint32_t*)(sQ + rb + 8*QS + d0 + 8);
        }
    }

    float4 o[8];
    #pragma unroll
    for (int nt = 0; nt < 8; nt++) o[nt] = make_float4(0.f,0.f,0.f,0.f);
    float l_lo = 0.f, l_hi = 0.f;

    float row_lo = (float)(q0 + wq*16 + g);
    float row_hi = row_lo + 8.0f;

    for (int it = 0; it < ntile; it++){
        int ksb = klo + it*64;
        if (it + 1 < ntile){
            __nv_bfloat16* dK = sK + ((it+1)&1)*SKH;
            __nv_bfloat16* dV = sVt + ((it+1)&1)*SVH;
            int kn = klo + (it+1)*64;
            #pragma unroll
            for (int f = tid; f < 512; f += 256){
                int kk = f >> 3, c8 = f & 7;
                cp16(dK + kk*QS + c8*8, Kb + (size_t)(kn + kk)*DH + c8*8);
                cp16(dV + kk*QS + c8*8, Vt + (size_t)kk*TT + kn + c8*8);
            }
            CP_COMMIT;
            CP_WAIT1;
        } else {
            CP_WAIT0;
        }
        __syncthreads();
        const __nv_bfloat16* sKc = sK + (it&1)*SKH;
        const __nv_bfloat16* sVc = sVt + (it&1)*SVH;

        // ---- scores over 64 keys (branch bw): 2 k16-steps x 8 ntiles ----
        float4 s[8];
        #pragma unroll
        for (int nt = 0; nt < 8; nt++) s[nt] = make_float4(0.f,0.f,0.f,0.f);
        #pragma unroll
        for (int ks = 0; ks < 2; ks++){
            int d0 = bw*32 + ks*16 + 2*q;
            #pragma unroll
            for (int nt = 0; nt < 8; nt++){
                uint32_t b[2];
                const __nv_bfloat16* kp = sKc + (nt*8 + g)*QS + d0;
                b[0] = *(const uint32_t*)(kp);
                b[1] = *(const uint32_t*)(kp + 8);
                mma16bf(s[nt], qa[ks], b, s[nt]);
            }
        }

        // ---- bias + exp (fixed reference) -> P bf16 ----
        #pragma unroll
        for (int nt = 0; nt < 8; nt++){
            float k0f = (float)(ksb + nt*8 + 2*q);
            float rx_lo = k0f - row_lo,  ry_lo = k0f + 1.0f - row_lo;
            float rx_hi = k0f - row_hi,  ry_hi = k0f + 1.0f - row_hi;
            float ax = exp2f(s[nt].x*sc2 + rx_lo*rx_lo*cb);
            float ay = exp2f(s[nt].y*sc2 + ry_lo*ry_lo*cb);
            float az = exp2f(s[nt].z*sc2 + rx_hi*rx_hi*cb);
            float aw = exp2f(s[nt].w*sc2 + ry_hi*ry_hi*cb);
            __nv_bfloat162 hlo = __floats2bfloat162_rn(ax, ay);
            __nv_bfloat162 hhi = __floats2bfloat162_rn(az, aw);
            *(__nv_bfloat162*)(sP + g*72 + nt*8 + 2*q)     = hlo;
            *(__nv_bfloat162*)(sP + (g+8)*72 + nt*8 + 2*q) = hhi;
            float2 flo = __bfloat1622float2(hlo);
            float2 fhi = __bfloat1622float2(hhi);
            l_lo += flo.x + flo.y;  l_hi += fhi.x + fhi.y;
        }
        __syncwarp();

        // ---- PV: O += P V (A = P bf16 [16x64], B = V^T bf16) ----
        #pragma unroll
        for (int ks = 0; ks < 4; ks++){
            uint32_t a[4];
            int pk = ks*16 + 2*q;
            a[0] = *(const uint32_t*)(sP + g*72 + pk);
            a[1] = *(const uint32_t*)(sP + (g+8)*72 + pk);
            a[2] = *(const uint32_t*)(sP + g*72 + pk + 8);
            a[3] = *(const uint32_t*)(sP + (g+8)*72 + pk + 8);
            #pragma unroll
            for (int nt = 0; nt < 8; nt++){
                uint32_t b[2];
                const __nv_bfloat16* vp = sVc + (nt*8 + g)*QS + ks*16 + 2*q;
                b[0] = *(const uint32_t*)(vp);
                b[1] = *(const uint32_t*)(vp + 8);
                mma16bf(o[nt], a, b, o[nt]);
            }
        }
        __syncwarp();
        __syncthreads();
    }

    // ---- reduce l over quad ----
    #pragma unroll
    for (int os = 1; os <= 2; os <<= 1){
        l_lo += __shfl_xor_sync(0xffffffffu, l_lo, os);
        l_hi += __shfl_xor_sync(0xffffffffu, l_hi, os);
    }

    // ---- branch combine via overlay float buffer [64][72] over sPb ----
    float* sC = (float*)sPb;
    if (bw == 1){
        float s_lo = lam / l_lo, s_hi = lam / l_hi;
        int rb0 = (wq*16 + g)*72, rb1 = (wq*16 + g + 8)*72;
        #pragma unroll
        for (int nt = 0; nt < 8; nt++){
            *(float2*)(sC + rb0 + nt*8 + 2*q) = make_float2(o[nt].x*s_lo, o[nt].y*s_lo);
            *(float2*)(sC + rb1 + nt*8 + 2*q) = make_float2(o[nt].z*s_hi, o[nt].w*s_hi);
        }
    }
    __syncthreads();
    if (bw == 0){
        float i_lo = 1.0f / l_lo, i_hi = 1.0f / l_hi;
        int rb0 = (wq*16 + g)*72, rb1 = (wq*16 + g + 8)*72;
        float4 ov[8];
        float slo = 0.f, shi = 0.f;
        #pragma unroll
        for (int nt = 0; nt < 8; nt++){
            float2 c0 = *(const float2*)(sC + rb0 + nt*8 + 2*q);
            float2 c1 = *(const float2*)(sC + rb1 + nt*8 + 2*q);
            ov[nt].x = o[nt].x*i_lo - c0.x;
            ov[nt].y = o[nt].y*i_lo - c0.y;
            ov[nt].z = o[nt].z*i_hi - c1.x;
            ov[nt].w = o[nt].w*i_hi - c1.y;
            slo += ov[nt].x + ov[nt].y;
            shi += ov[nt].z + ov[nt].w;
        }
        #pragma unroll
        for (int os = 1; os <= 2; os <<= 1){
            slo += __shfl_xor_sync(0xffffffffu, slo, os);
            shi += __shfl_xor_sync(0xffffffffu, shi, os);
        }
        float mulo = slo * (1.0f / DH), muhi = shi * (1.0f / DH);
        float vlo = 0.f, vhi = 0.f;
        #pragma unroll
        for (int nt = 0; nt < 8; nt++){
            float a0 = ov[nt].x - mulo, a1 = ov[nt].y - mulo;
            float a2 = ov[nt].z - muhi, a3 = ov[nt].w - muhi;
            vlo += a0*a0 + a1*a1;  vhi += a2*a2 + a3*a3;
        }
        #pragma unroll
        for (int os = 1; os <= 2; os <<= 1){
            vlo += __shfl_xor_sync(0xffffffffu, vlo, os);
            vhi += __shfl_xor_sync(0xffffffffu, vhi, os);
        }
        float rslo = rsqrtf(vlo * (1.0f / DH) + LN_EPS);
        float rshi = rsqrtf(vhi * (1.0f / DH) + LN_EPS);

        int b_ = bh >> 2, h = bh & 3;
        int tok_lo = b_*TT + q0 + wq*16 + g;
        float* OdLo = g_O + (size_t)tok_lo*256 + h*DH;
        float* OdHi = OdLo + 8*256;
        #pragma unroll
        for (int nt = 0; nt < 8; nt++){
            float2 wv2 = *(const float2*)(hnw + nt*8 + 2*q);
            float2 bv2 = *(const float2*)(hnb + nt*8 + 2*q);
            float y0 = ((ov[nt].x - mulo)*rslo*wv2.x + bv2.x) * (1.0f - LAMBDA_INIT);
            float y1 = ((ov[nt].y - mulo)*rslo*wv2.y + bv2.y) * (1.0f - LAMBDA_INIT);
            float y2 = ((ov[nt].z - muhi)*rshi*wv2.x + bv2.x) * (1.0f - LAMBDA_INIT);
            float y3 = ((ov[nt].w - muhi)*rshi*wv2.y + bv2.y) * (1.0f - LAMBDA_INIT);
            *(float2*)(OdLo + nt*8 + 2*q) = make_float2(y0, y1);
            *(float2*)(OdHi + nt*8 + 2*q) = make_float2(y2, y3);
        }
    }
}

// ================= K3: output GEMM tf32 (16384 x 128 x 256) + residual, 3-stage =================
#define OUT_SAT (64*36)
#define OUT_SBT (32*136)
__global__ __launch_bounds__(256) void out_gemm(const float* __restrict__ wo,
                                                const float* __restrict__ tokens,
                                                float* __restrict__ out){
    extern __shared__ float dynsm[];
    float* sA = dynsm;                 // 3 stages [64][36]
    float* sB = dynsm + 3*OUT_SAT;     // 3 stages [32][136]

    int brow = blockIdx.x;             // 0..255
    int tid = threadIdx.x;
    int w = tid >> 5, lane = tid & 31, g = lane >> 2, q = lane & 3;
    int wm = w >> 2, wn = w & 3;
    float4 acc[2][4];
    #pragma unroll
    for (int i = 0; i < 2; i++)
        #pragma unroll
        for (int j = 0; j < 4; j++) acc[i][j] = make_float4(0.f,0.f,0.f,0.f);

    #pragma unroll
    for (int pc = 0; pc < 2; pc++){
        float* dA = sA + pc*OUT_SAT;
        float* dB = sB + pc*OUT_SBT;
        #pragma unroll
        for (int f = tid; f < 512; f += 256){
            int r = f >> 3, c4 = f & 7;
            cp16(dA + r*36 + c4*4, g_O + (size_t)(brow*64 + r)*256 + pc*32 + c4*4);
        }
        #pragma unroll
        for (int f = tid; f < 1024; f += 256){
            int kr = f >> 5, c4 = f & 31;
            cp16(dB + kr*136 + c4*4, wo + (size_t)(pc*32 + kr)*DD + c4*4);
        }
        CP_COMMIT;
    }

    for (int kc = 0; kc < 8; kc++){
        if (kc + 2 < 8){
            int st = (kc + 2) % 3;
            float* dA = sA + st*OUT_SAT;
            float* dB = sB + st*OUT_SBT;
            #pragma unroll
            for (int f = tid; f < 512; f += 256){
                int r = f >> 3, c4 = f & 7;
                cp16(dA + r*36 + c4*4, g_O + (size_t)(brow*64 + r)*256 + (kc+2)*32 + c4*4);
            }
            #pragma unroll
            for (int f = tid; f < 1024; f += 256){
                int kr = f >> 5, c4 = f & 31;
                cp16(dB + kr*136 + c4*4, wo + (size_t)((kc+2)*32 + kr)*DD + c4*4);
            }
            CP_COMMIT;
            CP_WAIT2;
        } else if (kc + 1 < 8){
            CP_WAIT1;
        } else {
            CP_WAIT0;
        }
        __syncthreads();
        const float* sAc = sA + (kc%3)*OUT_SAT;
        const float* sBc = sB + (kc%3)*OUT_SBT;
        #pragma unroll
        for (int ks = 0; ks < 4; ks++){
            uint32_t a[2][4];
            int kk = ks*8 + q;
            #pragma unroll
            for (int mt = 0; mt < 2; mt++){
                int r = wm*32 + mt*16 + g;
                a[mt][0] = __float_as_uint(sAc[r*36 + kk]);
                a[mt][1] = __float_as_uint(sAc[(r+8)*36 + kk]);
                a[mt][2] = __float_as_uint(sAc[r*36 + kk + 4]);
                a[mt][3] = __float_as_uint(sAc[(r+8)*36 + kk + 4]);
            }
            #pragma unroll
            for (int nt = 0; nt < 4; nt++){
                uint32_t b[2];
                int n = wn*32 + nt*8 + g;
                b[0] = __float_as_uint(sBc[kk*136 + n]);
                b[1] = __float_as_uint(sBc[(kk+4)*136 + n]);
                #pragma unroll
                for (int mt = 0; mt < 2; mt++)
                    mma8(acc[mt][nt], a[mt], b, acc[mt][nt]);
            }
        }
        __syncthreads();
    }

    #pragma unroll
    for (int mt = 0; mt < 2; mt++){
        int r0 = brow*64 + wm*32 + mt*16 + g;
        int r1 = r0 + 8;
        #pragma unroll
        for (int nt = 0; nt < 4; nt++){
            int col = wn*32 + nt*8 + 2*q;
            float2 t0 = *(const float2*)(tokens + (size_t)r0*DD + col);
            float2 t1 = *(const float2*)(tokens + (size_t)r1*DD + col);
            *(float2*)(out + (size_t)r0*DD + col) = make_float2(acc[mt][nt].x + t0.x, acc[mt][nt].y + t0.y);
            *(float2*)(out + (size_t)r1*DD + col) = make_float2(acc[mt][nt].z + t1.x, acc[mt][nt].w + t1.y);
        }
    }
}

// ================= launch =================
#define QKV_SMEM ((3*QKV_SAT + 3*QKV_SBT) * 4)
#define ATTN_SMEM ((64*QS + 2*SKH + 2*SVH + 8*SPH) * 2)
#define OUT_SMEM ((3*OUT_SAT + 3*OUT_SBT) * 4)

extern "C" void kernel_launch(void* const* d_in, const int* in_sizes, int n_in,
                              void* d_out, int out_size){
    const float* tokens = (const float*)d_in[0];
    const float* ln_w   = (const float*)d_in[1];
    const float* ln_b   = (const float*)d_in[2];
    const float* wq     = (const float*)d_in[3];
    const float* wk     = (const float*)d_in[4];
    const float* wv     = (const float*)d_in[5];
    const float* wo     = (const float*)d_in[6];
    const float* lq1    = (const float*)d_in[7];
    const float* lk1    = (const float*)d_in[8];
    const float* lq2    = (const float*)d_in[9];
    const float* lk2    = (const float*)d_in[10];
    const float* sig_s  = (const float*)d_in[11];
    const float* sig_n  = (const float*)d_in[12];
    const float* hnw    = (const float*)d_in[13];
    const float* hnb    = (const float*)d_in[14];
    float* out = (float*)d_out;

    static int attr_done = 0;
    if (!attr_done){
        cudaFuncSetAttribute(qkv_gemm, cudaFuncAttributeMaxDynamicSharedMemorySize, QKV_SMEM);
        cudaFuncSetAttribute(attn_kernel, cudaFuncAttributeMaxDynamicSharedMemorySize, ATTN_SMEM);
        cudaFuncSetAttribute(out_gemm, cudaFuncAttributeMaxDynamicSharedMemorySize, OUT_SMEM);
        attr_done = 1;
    }

    ln_kernel<<<NTOK/8, dim3(32,8)>>>(tokens, ln_w, ln_b);
    qkv_gemm<<<dim3(NTOK/128, 6), 256, QKV_SMEM>>>(wq, wk, wv);
    attn_kernel<<<dim3(TT/64, BB*HH), 256, ATTN_SMEM>>>(lq1, lk1, lq2, lk2, sig_s, sig_n, hnw, hnb);
    out_gemm<<<NTOK/64, 256, OUT_SMEM>>>(wo, tokens, out);
}